// round 3
// baseline (speedup 1.0000x reference)
#include <cuda_runtime.h>
#include <cuda_bf16.h>

#define NN   100000
#define NE   1600000
#define HID  128
#define NOUT 64

// ---------------- scratch (device globals; no allocations allowed) -----------
__device__ int   g_cnt[NN];
__device__ int   g_rowptr[NN + 1];
__device__ int   g_cursor[NN];
__device__ float g_dis[NN];
__device__ int   g_ecol[NE];
__device__ float g_enorm[NE];
__device__ float g_hA[(size_t)NN * HID];   // h1
__device__ float g_hB[(size_t)NN * HID];   // h2
__device__ float g_acc[(size_t)NN * HID];  // mean(x,h1,h2,h3)

__device__ __forceinline__ int clampN(int v) {
    v = v < 0 ? 0 : v;
    return v >= NN ? NN - 1 : v;
}

// ---------------- CSR build ---------------------------------------------------
__global__ void k_zero() {
    int i = blockIdx.x * blockDim.x + threadIdx.x;
    if (i < NN) g_cnt[i] = 0;
}

__global__ void k_count(const int* __restrict__ ei) {
    int e = blockIdx.x * blockDim.x + threadIdx.x;
    if (e < NE) atomicAdd(&g_cnt[clampN(ei[e])], 1);
}

// single-block exclusive scan of g_cnt -> g_rowptr (4 elems / thread / chunk)
__global__ void k_scan() {
    __shared__ int s_warp[32];
    __shared__ int s_carry;
    const int tid = threadIdx.x, lane = tid & 31, wid = tid >> 5;
    if (tid == 0) { s_carry = 0; g_rowptr[0] = 0; }
    __syncthreads();
    for (int base = 0; base < NN; base += 4096) {
        int idx = base + tid * 4;
        int v0 = 0, v1 = 0, v2 = 0, v3 = 0;
        if (idx + 3 < NN) {
            int4 q = *(const int4*)&g_cnt[idx];
            v0 = q.x; v1 = q.y; v2 = q.z; v3 = q.w;
        } else {
            if (idx + 0 < NN) v0 = g_cnt[idx + 0];
            if (idx + 1 < NN) v1 = g_cnt[idx + 1];
            if (idx + 2 < NN) v2 = g_cnt[idx + 2];
            if (idx + 3 < NN) v3 = g_cnt[idx + 3];
        }
        int s = v0 + v1 + v2 + v3;
        int x = s;
        #pragma unroll
        for (int d = 1; d < 32; d <<= 1) {
            int t = __shfl_up_sync(0xffffffffu, x, d);
            if (lane >= d) x += t;
        }
        if (lane == 31) s_warp[wid] = x;
        __syncthreads();
        if (wid == 0) {
            int y = s_warp[lane];
            #pragma unroll
            for (int d = 1; d < 32; d <<= 1) {
                int t = __shfl_up_sync(0xffffffffu, y, d);
                if (lane >= d) y += t;
            }
            s_warp[lane] = y;
        }
        __syncthreads();
        int incl = x + (wid > 0 ? s_warp[wid - 1] : 0) + s_carry;
        int p = incl - s;  // exclusive start for this thread's 4 elems
        if (idx + 0 < NN) { p += v0; g_rowptr[idx + 1] = p; }
        if (idx + 1 < NN) { p += v1; g_rowptr[idx + 2] = p; }
        if (idx + 2 < NN) { p += v2; g_rowptr[idx + 3] = p; }
        if (idx + 3 < NN) { p += v3; g_rowptr[idx + 4] = p; }
        __syncthreads();
        if (tid == blockDim.x - 1) s_carry = incl;
        __syncthreads();
    }
}

__global__ void k_prep() {
    int i = blockIdx.x * blockDim.x + threadIdx.x;
    if (i < NN) {
        g_dis[i]    = rsqrtf(fmaxf((float)g_cnt[i], 1.0f));
        g_cursor[i] = g_rowptr[i];
    }
}

__global__ void k_scatter(const int* __restrict__ ei) {
    int e = blockIdx.x * blockDim.x + threadIdx.x;
    if (e < NE) {
        int r = clampN(ei[e]);
        int c = clampN(ei[NE + e]);
        int pos = atomicAdd(&g_cursor[r], 1);
        g_ecol[pos]  = c;
        g_enorm[pos] = g_dis[r] * g_dis[c];
    }
}

// ---------------- propagate: warp per node, float4 per lane -------------------
// STAGE 0: src = x (param)   -> dst = g_hA
// STAGE 1: src = g_hA        -> dst = g_hB
// STAGE 2: src = g_hB        -> dst = g_acc = 0.25*(x + hA + hB + h3)
template <int STAGE>
__global__ void k_prop(const float4* __restrict__ xin) {
    const int gw   = (blockIdx.x * blockDim.x + threadIdx.x) >> 5;
    const int lane = threadIdx.x & 31;
    if (gw >= NN) return;

    const float4* __restrict__ src =
        (STAGE == 0) ? xin :
        (STAGE == 1) ? (const float4*)g_hA : (const float4*)g_hB;
    float4* __restrict__ dst =
        (STAGE == 0) ? (float4*)g_hA :
        (STAGE == 1) ? (float4*)g_hB : (float4*)g_acc;

    const int beg = g_rowptr[gw];
    const int end = g_rowptr[gw + 1];

    float ax = 0.f, ay = 0.f, az = 0.f, aw = 0.f;

    for (int e0 = beg; e0 < end; e0 += 32) {
        int e = e0 + lane;
        int   cc = 0;
        float ww = 0.f;
        if (e < end) { cc = g_ecol[e]; ww = g_enorm[e]; }
        int m = end - e0; if (m > 32) m = 32;
        int j = 0;
        for (; j + 4 <= m; j += 4) {
            int   c0 = __shfl_sync(0xffffffffu, cc, j + 0);
            int   c1 = __shfl_sync(0xffffffffu, cc, j + 1);
            int   c2 = __shfl_sync(0xffffffffu, cc, j + 2);
            int   c3 = __shfl_sync(0xffffffffu, cc, j + 3);
            float w0 = __shfl_sync(0xffffffffu, ww, j + 0);
            float w1 = __shfl_sync(0xffffffffu, ww, j + 1);
            float w2 = __shfl_sync(0xffffffffu, ww, j + 2);
            float w3 = __shfl_sync(0xffffffffu, ww, j + 3);
            float4 v0 = __ldg(&src[(size_t)c0 * 32 + lane]);
            float4 v1 = __ldg(&src[(size_t)c1 * 32 + lane]);
            float4 v2 = __ldg(&src[(size_t)c2 * 32 + lane]);
            float4 v3 = __ldg(&src[(size_t)c3 * 32 + lane]);
            ax += w0 * v0.x + w1 * v1.x + w2 * v2.x + w3 * v3.x;
            ay += w0 * v0.y + w1 * v1.y + w2 * v2.y + w3 * v3.y;
            az += w0 * v0.z + w1 * v1.z + w2 * v2.z + w3 * v3.z;
            aw += w0 * v0.w + w1 * v1.w + w2 * v2.w + w3 * v3.w;
        }
        for (; j < m; ++j) {
            int   c0 = __shfl_sync(0xffffffffu, cc, j);
            float w0 = __shfl_sync(0xffffffffu, ww, j);
            float4 v0 = __ldg(&src[(size_t)c0 * 32 + lane]);
            ax += w0 * v0.x; ay += w0 * v0.y; az += w0 * v0.z; aw += w0 * v0.w;
        }
    }

    const size_t o = (size_t)gw * 32 + lane;
    if (STAGE == 2) {
        float4 xv  = xin[o];
        float4 h1v = ((const float4*)g_hA)[o];
        float4 h2v = ((const float4*)g_hB)[o];
        float4 r;
        r.x = 0.25f * (xv.x + h1v.x + h2v.x + ax);
        r.y = 0.25f * (xv.y + h1v.y + h2v.y + ay);
        r.z = 0.25f * (xv.z + h1v.z + h2v.z + az);
        r.w = 0.25f * (xv.w + h1v.w + h2v.w + aw);
        dst[o] = r;
    } else {
        dst[o] = make_float4(ax, ay, az, aw);
    }
}

// ---------------- final dense: out = acc @ W^T + b ---------------------------
__global__ void k_gemm(const float* __restrict__ W, const float* __restrict__ b,
                       float* __restrict__ out) {
    __shared__ float4 Wsh[NOUT * HID / 4];  // W row-major [o][k], as float4
    __shared__ float  bsh[NOUT];
    const int tid = threadIdx.x;
    const float4* W4 = (const float4*)W;
    for (int i = tid; i < NOUT * HID / 4; i += blockDim.x) Wsh[i] = W4[i];
    if (tid < NOUT) bsh[tid] = b[tid];
    __syncthreads();

    const int v = blockIdx.x * blockDim.x + tid;
    if (v >= NN) return;

    const float4* a4 = (const float4*)g_acc + (size_t)v * 32;
    float s[NOUT];
    #pragma unroll
    for (int o = 0; o < NOUT; ++o) s[o] = 0.f;

    for (int kk = 0; kk < 32; ++kk) {
        float4 a = __ldg(&a4[kk]);
        #pragma unroll
        for (int o = 0; o < NOUT; ++o) {
            float4 wv = Wsh[o * 32 + kk];
            s[o] = fmaf(a.x, wv.x, fmaf(a.y, wv.y, fmaf(a.z, wv.z, fmaf(a.w, wv.w, s[o]))));
        }
    }

    float4* op = (float4*)(out + (size_t)v * NOUT);
    #pragma unroll
    for (int o = 0; o < NOUT; o += 4) {
        float4 r = make_float4(s[o] + bsh[o], s[o + 1] + bsh[o + 1],
                               s[o + 2] + bsh[o + 2], s[o + 3] + bsh[o + 3]);
        op[o / 4] = r;
    }
}

// ---------------- launch -----------------------------------------------------
extern "C" void kernel_launch(void* const* d_in, const int* in_sizes, int n_in,
                              void* d_out, int out_size) {
    const float* x   = (const float*)d_in[0];   // [NN, HID]
    const int*   ei  = (const int*)d_in[1];     // [2, NE] int32 (JAX x64 disabled)
    const float* W   = (const float*)d_in[2];   // [NOUT, HID]
    const float* b   = (const float*)d_in[3];   // [NOUT]
    float*       out = (float*)d_out;           // [NN, NOUT]

    const int TB = 256;
    const int gN = (NN + TB - 1) / TB;
    const int gE = (NE + TB - 1) / TB;
    const int gP = (NN * 32 + TB - 1) / TB;  // warp per node

    k_zero<<<gN, TB>>>();
    k_count<<<gE, TB>>>(ei);
    k_scan<<<1, 1024>>>();
    k_prep<<<gN, TB>>>();
    k_scatter<<<gE, TB>>>(ei);

    const float4* x4 = (const float4*)x;
    k_prop<0><<<gP, TB>>>(x4);  // x  -> hA
    k_prop<1><<<gP, TB>>>(x4);  // hA -> hB
    k_prop<2><<<gP, TB>>>(x4);  // hB -> acc (fused mean)

    const int gG = (NN + 127) / 128;
    k_gemm<<<gG, 128>>>(W, b, out);
}

// round 5
// speedup vs baseline: 1.1210x; 1.1210x over previous
#include <cuda_runtime.h>
#include <cuda_fp16.h>

#define NN   100000
#define NE   1600000
#define HID  128
#define NOUT 64

// ---------------- scratch (device globals; no allocations allowed) -----------
__device__ int   g_cnt[NN];
__device__ int   g_rowptr[NN + 1];
__device__ int   g_cursor[NN];
__device__ float g_dis[NN];
__device__ int   g_ecol[NE];
__device__ float g_enorm[NE];
__device__ uint2 g_xh[(size_t)NN * 32];   // x in half  (128 half = 32 uint2)
__device__ uint2 g_hA[(size_t)NN * 32];   // h1 in half
__device__ uint2 g_hB[(size_t)NN * 32];   // h2 in half
__device__ float g_acc[(size_t)NN * HID]; // mean(x,h1,h2,h3) fp32

__device__ __forceinline__ int clampN(int v) {
    v = v < 0 ? 0 : v;
    return v >= NN ? NN - 1 : v;
}

__device__ __forceinline__ uint2 pack4h(float a, float b, float c, float d) {
    __half2 h0 = __floats2half2_rn(a, b);
    __half2 h1 = __floats2half2_rn(c, d);
    uint2 r;
    r.x = *reinterpret_cast<unsigned*>(&h0);
    r.y = *reinterpret_cast<unsigned*>(&h1);
    return r;
}

__device__ __forceinline__ void unpack4h(uint2 v, float& a, float& b, float& c, float& d) {
    __half2 h0 = *reinterpret_cast<__half2*>(&v.x);
    __half2 h1 = *reinterpret_cast<__half2*>(&v.y);
    float2 f0 = __half22float2(h0);
    float2 f1 = __half22float2(h1);
    a = f0.x; b = f0.y; c = f1.x; d = f1.y;
}

// ---------------- x -> half conversion (+ zero counts, fused) ----------------
__global__ void k_x2h(const float4* __restrict__ x4) {
    int i = blockIdx.x * blockDim.x + threadIdx.x;
    if (i < NN) g_cnt[i] = 0;
    if (i < NN * 32) {
        float4 v = x4[i];
        g_xh[i] = pack4h(v.x, v.y, v.z, v.w);
    }
}

// ---------------- CSR build ---------------------------------------------------
__global__ void k_count(const int* __restrict__ ei) {
    int e = blockIdx.x * blockDim.x + threadIdx.x;
    if (e < NE) atomicAdd(&g_cnt[clampN(ei[e])], 1);
}

// single-block exclusive scan of g_cnt -> g_rowptr (4 elems / thread / chunk)
__global__ void k_scan() {
    __shared__ int s_warp[32];
    __shared__ int s_carry;
    const int tid = threadIdx.x, lane = tid & 31, wid = tid >> 5;
    if (tid == 0) { s_carry = 0; g_rowptr[0] = 0; }
    __syncthreads();
    for (int base = 0; base < NN; base += 4096) {
        int idx = base + tid * 4;
        int v0 = 0, v1 = 0, v2 = 0, v3 = 0;
        if (idx + 3 < NN) {
            int4 q = *(const int4*)&g_cnt[idx];
            v0 = q.x; v1 = q.y; v2 = q.z; v3 = q.w;
        } else {
            if (idx + 0 < NN) v0 = g_cnt[idx + 0];
            if (idx + 1 < NN) v1 = g_cnt[idx + 1];
            if (idx + 2 < NN) v2 = g_cnt[idx + 2];
            if (idx + 3 < NN) v3 = g_cnt[idx + 3];
        }
        int s = v0 + v1 + v2 + v3;
        int x = s;
        #pragma unroll
        for (int d = 1; d < 32; d <<= 1) {
            int t = __shfl_up_sync(0xffffffffu, x, d);
            if (lane >= d) x += t;
        }
        if (lane == 31) s_warp[wid] = x;
        __syncthreads();
        if (wid == 0) {
            int y = s_warp[lane];
            #pragma unroll
            for (int d = 1; d < 32; d <<= 1) {
                int t = __shfl_up_sync(0xffffffffu, y, d);
                if (lane >= d) y += t;
            }
            s_warp[lane] = y;
        }
        __syncthreads();
        int incl = x + (wid > 0 ? s_warp[wid - 1] : 0) + s_carry;
        int p = incl - s;
        if (idx + 0 < NN) { p += v0; g_rowptr[idx + 1] = p; }
        if (idx + 1 < NN) { p += v1; g_rowptr[idx + 2] = p; }
        if (idx + 2 < NN) { p += v2; g_rowptr[idx + 3] = p; }
        if (idx + 3 < NN) { p += v3; g_rowptr[idx + 4] = p; }
        __syncthreads();
        if (tid == blockDim.x - 1) s_carry = incl;
        __syncthreads();
    }
}

__global__ void k_prep() {
    int i = blockIdx.x * blockDim.x + threadIdx.x;
    if (i < NN) {
        g_dis[i]    = rsqrtf(fmaxf((float)g_cnt[i], 1.0f));
        g_cursor[i] = g_rowptr[i];
    }
}

__global__ void k_scatter(const int* __restrict__ ei) {
    int e = blockIdx.x * blockDim.x + threadIdx.x;
    if (e < NE) {
        int r = clampN(ei[e]);
        int c = clampN(ei[NE + e]);
        int pos = atomicAdd(&g_cursor[r], 1);
        g_ecol[pos]  = c;
        g_enorm[pos] = g_dis[r] * g_dis[c];
    }
}

// ---------------- propagate: warp per node, half rows (256B), fp32 accum -----
// STAGE 0: src = g_xh -> dst = g_hA (half)
// STAGE 1: src = g_hA -> dst = g_hB (half)
// STAGE 2: src = g_hB -> g_acc = 0.25*(x + hA + hB + h3) (fp32)
template <int STAGE>
__global__ void k_prop(const float4* __restrict__ xin) {
    const int gw   = (blockIdx.x * blockDim.x + threadIdx.x) >> 5;
    const int lane = threadIdx.x & 31;
    if (gw >= NN) return;

    const uint2* __restrict__ src =
        (STAGE == 0) ? g_xh : (STAGE == 1) ? g_hA : g_hB;

    const int beg = g_rowptr[gw];
    const int end = g_rowptr[gw + 1];

    float ax = 0.f, ay = 0.f, az = 0.f, aw = 0.f;

    for (int e0 = beg; e0 < end; e0 += 32) {
        int e = e0 + lane;
        int   cc = 0;
        float ww = 0.f;
        if (e < end) { cc = g_ecol[e]; ww = g_enorm[e]; }
        int m = end - e0; if (m > 32) m = 32;
        int j = 0;
        for (; j + 8 <= m; j += 8) {
            int   c0 = __shfl_sync(0xffffffffu, cc, j + 0);
            int   c1 = __shfl_sync(0xffffffffu, cc, j + 1);
            int   c2 = __shfl_sync(0xffffffffu, cc, j + 2);
            int   c3 = __shfl_sync(0xffffffffu, cc, j + 3);
            int   c4 = __shfl_sync(0xffffffffu, cc, j + 4);
            int   c5 = __shfl_sync(0xffffffffu, cc, j + 5);
            int   c6 = __shfl_sync(0xffffffffu, cc, j + 6);
            int   c7 = __shfl_sync(0xffffffffu, cc, j + 7);
            float w0 = __shfl_sync(0xffffffffu, ww, j + 0);
            float w1 = __shfl_sync(0xffffffffu, ww, j + 1);
            float w2 = __shfl_sync(0xffffffffu, ww, j + 2);
            float w3 = __shfl_sync(0xffffffffu, ww, j + 3);
            float w4 = __shfl_sync(0xffffffffu, ww, j + 4);
            float w5 = __shfl_sync(0xffffffffu, ww, j + 5);
            float w6 = __shfl_sync(0xffffffffu, ww, j + 6);
            float w7 = __shfl_sync(0xffffffffu, ww, j + 7);
            uint2 v0 = __ldg(&src[(size_t)c0 * 32 + lane]);
            uint2 v1 = __ldg(&src[(size_t)c1 * 32 + lane]);
            uint2 v2 = __ldg(&src[(size_t)c2 * 32 + lane]);
            uint2 v3 = __ldg(&src[(size_t)c3 * 32 + lane]);
            uint2 v4 = __ldg(&src[(size_t)c4 * 32 + lane]);
            uint2 v5 = __ldg(&src[(size_t)c5 * 32 + lane]);
            uint2 v6 = __ldg(&src[(size_t)c6 * 32 + lane]);
            uint2 v7 = __ldg(&src[(size_t)c7 * 32 + lane]);
            float fx, fy, fz, fw;
            unpack4h(v0, fx, fy, fz, fw); ax = fmaf(w0, fx, ax); ay = fmaf(w0, fy, ay); az = fmaf(w0, fz, az); aw = fmaf(w0, fw, aw);
            unpack4h(v1, fx, fy, fz, fw); ax = fmaf(w1, fx, ax); ay = fmaf(w1, fy, ay); az = fmaf(w1, fz, az); aw = fmaf(w1, fw, aw);
            unpack4h(v2, fx, fy, fz, fw); ax = fmaf(w2, fx, ax); ay = fmaf(w2, fy, ay); az = fmaf(w2, fz, az); aw = fmaf(w2, fw, aw);
            unpack4h(v3, fx, fy, fz, fw); ax = fmaf(w3, fx, ax); ay = fmaf(w3, fy, ay); az = fmaf(w3, fz, az); aw = fmaf(w3, fw, aw);
            unpack4h(v4, fx, fy, fz, fw); ax = fmaf(w4, fx, ax); ay = fmaf(w4, fy, ay); az = fmaf(w4, fz, az); aw = fmaf(w4, fw, aw);
            unpack4h(v5, fx, fy, fz, fw); ax = fmaf(w5, fx, ax); ay = fmaf(w5, fy, ay); az = fmaf(w5, fz, az); aw = fmaf(w5, fw, aw);
            unpack4h(v6, fx, fy, fz, fw); ax = fmaf(w6, fx, ax); ay = fmaf(w6, fy, ay); az = fmaf(w6, fz, az); aw = fmaf(w6, fw, aw);
            unpack4h(v7, fx, fy, fz, fw); ax = fmaf(w7, fx, ax); ay = fmaf(w7, fy, ay); az = fmaf(w7, fz, az); aw = fmaf(w7, fw, aw);
        }
        for (; j < m; ++j) {
            int   c0 = __shfl_sync(0xffffffffu, cc, j);
            float w0 = __shfl_sync(0xffffffffu, ww, j);
            uint2 v0 = __ldg(&src[(size_t)c0 * 32 + lane]);
            float fx, fy, fz, fw;
            unpack4h(v0, fx, fy, fz, fw);
            ax = fmaf(w0, fx, ax); ay = fmaf(w0, fy, ay); az = fmaf(w0, fz, az); aw = fmaf(w0, fw, aw);
        }
    }

    const size_t o = (size_t)gw * 32 + lane;
    if (STAGE == 2) {
        float4 xv = xin[o];
        float a0, a1, a2, a3, b0, b1, b2, b3;
        unpack4h(__ldg(&g_hA[o]), a0, a1, a2, a3);
        unpack4h(__ldg(&g_hB[o]), b0, b1, b2, b3);
        float4 r;
        r.x = 0.25f * (xv.x + a0 + b0 + ax);
        r.y = 0.25f * (xv.y + a1 + b1 + ay);
        r.z = 0.25f * (xv.z + a2 + b2 + az);
        r.w = 0.25f * (xv.w + a3 + b3 + aw);
        ((float4*)g_acc)[o] = r;
    } else if (STAGE == 1) {
        g_hB[o] = pack4h(ax, ay, az, aw);
    } else {
        g_hA[o] = pack4h(ax, ay, az, aw);
    }
}

// ---------------- final dense: out = acc @ W^T + b (packed f32x2 FMA) --------
#define WT_PITCH 66  // 64 outputs + pad: keeps 8B alignment per row, spreads banks

__global__ void __launch_bounds__(128) k_gemm(const float* __restrict__ W,
                                              const float* __restrict__ b,
                                              float* __restrict__ out) {
    __shared__ float Wt[HID * WT_PITCH];  // transposed W: Wt[k*66 + o]
    __shared__ float bsh[NOUT];
    const int tid = threadIdx.x;
    for (int idx = tid; idx < NOUT * HID; idx += 128) {
        int o = idx >> 7;      // W row-major [o][k]
        int k = idx & 127;
        Wt[k * WT_PITCH + o] = W[idx];
    }
    if (tid < NOUT) bsh[tid] = b[tid];
    __syncthreads();

    const int v = blockIdx.x * 128 + tid;
    if (v >= NN) return;

    const float4* a4 = (const float4*)g_acc + (size_t)v * 32;

    unsigned long long s2[32];  // 32 f32x2 accumulators: pair (2*o2, 2*o2+1)
    #pragma unroll
    for (int i = 0; i < 32; ++i) s2[i] = 0ull;

    #pragma unroll 4
    for (int kk = 0; kk < 32; ++kk) {
        float4 a = __ldg(&a4[kk]);
        #pragma unroll
        for (int d = 0; d < 4; ++d) {
            float av = (d == 0) ? a.x : (d == 1) ? a.y : (d == 2) ? a.z : a.w;
            unsigned long long ap;
            asm("mov.b64 %0, {%1, %2};" : "=l"(ap) : "f"(av), "f"(av));
            const unsigned long long* w2 =
                reinterpret_cast<const unsigned long long*>(&Wt[(kk * 4 + d) * WT_PITCH]);
            #pragma unroll
            for (int o2 = 0; o2 < 32; ++o2) {
                asm("fma.rn.f32x2 %0, %1, %2, %0;" : "+l"(s2[o2]) : "l"(ap), "l"(w2[o2]));
            }
        }
    }

    float4* op = (float4*)(out + (size_t)v * NOUT);
    #pragma unroll
    for (int q = 0; q < 16; ++q) {
        float l0, h0, l1, h1;
        asm("mov.b64 {%0, %1}, %2;" : "=f"(l0), "=f"(h0) : "l"(s2[2 * q]));
        asm("mov.b64 {%0, %1}, %2;" : "=f"(l1), "=f"(h1) : "l"(s2[2 * q + 1]));
        float4 r = make_float4(l0 + bsh[4 * q + 0], h0 + bsh[4 * q + 1],
                               l1 + bsh[4 * q + 2], h1 + bsh[4 * q + 3]);
        op[q] = r;
    }
}

// ---------------- launch -----------------------------------------------------
extern "C" void kernel_launch(void* const* d_in, const int* in_sizes, int n_in,
                              void* d_out, int out_size) {
    const float* x   = (const float*)d_in[0];   // [NN, HID]
    const int*   ei  = (const int*)d_in[1];     // [2, NE] int32
    const float* W   = (const float*)d_in[2];   // [NOUT, HID]
    const float* b   = (const float*)d_in[3];   // [NOUT]
    float*       out = (float*)d_out;           // [NN, NOUT]

    const int TB = 256;
    const int gX = (NN * 32 + TB - 1) / TB;  // conversion grid (also zeroes cnt)
    const int gN = (NN + TB - 1) / TB;
    const int gE = (NE + TB - 1) / TB;
    const int gP = (NN * 32 + TB - 1) / TB;  // warp per node

    const float4* x4 = (const float4*)x;

    k_x2h<<<gX, TB>>>(x4);          // x -> half, zero counts
    k_count<<<gE, TB>>>(ei);
    k_scan<<<1, 1024>>>();
    k_prep<<<gN, TB>>>();
    k_scatter<<<gE, TB>>>(ei);

    k_prop<0><<<gP, TB>>>(x4);  // xh -> hA
    k_prop<1><<<gP, TB>>>(x4);  // hA -> hB
    k_prop<2><<<gP, TB>>>(x4);  // hB -> acc (fused mean, fp32)

    const int gG = (NN + 127) / 128;
    k_gemm<<<gG, 128>>>(W, b, out);
}